// round 14
// baseline (speedup 1.0000x reference)
#include <cuda_runtime.h>
#include <cuda_bf16.h>
#include <math.h>
#include <stdint.h>

#define NN 65536
#define GG 1024
#define SSZ 64
#define DD 64
#define OBSD 256
#define HIDD 512

// ---------------- scratch (device globals; no allocations allowed) ----------
__device__ __align__(16) float g_inter_emb[NN * DD];
__device__ __align__(16) float g_pooled[GG * DD];
__device__ __align__(16) float g_qkv[2][GG * 3 * DD];
__device__ __align__(16) float g_attno[2][GG * DD];
__device__ __align__(16) float g_inter_mu[GG * DD];
__device__ __align__(16) float g_inter_std[GG * DD];
__device__ __align__(16) float g_inter_sample[GG * DD];

// bf16 hi/lo split operands
__device__ __align__(16) __nv_bfloat16 g_Ah[(size_t)NN * OBSD];
__device__ __align__(16) __nv_bfloat16 g_Al[(size_t)NN * OBSD];
__device__ __align__(16) __nv_bfloat16 g_Wh[640 * OBSD];
__device__ __align__(16) __nv_bfloat16 g_Wl[640 * OBSD];
__device__ float g_bias[640];

// intra_emb as bf16 hi/lo (input to k2a GEMM)
__device__ __align__(16) __nv_bfloat16 g_Eh[(size_t)NN * DD];
__device__ __align__(16) __nv_bfloat16 g_El[(size_t)NN * DD];
// packed intra in-proj weights [384=192mu+192std][64] hi/lo + bias
__device__ __align__(16) __nv_bfloat16 g_Wqh[384 * DD];
__device__ __align__(16) __nv_bfloat16 g_Wql[384 * DD];
__device__ float g_qbias[384];
// QKV (bias included) for all agents: [65536][384] (0..191 mu, 192..383 std)
__device__ __align__(16) float g_qkv_all[(size_t)NN * 384];

__device__ __forceinline__ float softplusf(float x) {
    return (x > 20.f) ? x : __logf(1.f + __expf(x));
}
__device__ __forceinline__ float ftanh(float x) {
    float ax = fabsf(x);
    float t = __expf(-2.f * ax);
    float r = __fdividef(1.f - t, 1.f + t);
    return copysignf(r, x);
}

__device__ __forceinline__ uint32_t smem_u32(const void* p) {
    uint32_t a;
    asm("{ .reg .u64 t; cvta.to.shared.u64 t, %1; cvt.u32.u64 %0, t; }" : "=r"(a) : "l"(p));
    return a;
}
__device__ __forceinline__ uint32_t swz128(uint32_t off) {
    return off ^ ((off >> 3) & 0x70);
}
__device__ __forceinline__ uint32_t swz64(uint32_t off) {
    return off ^ ((off >> 3) & 0x30);
}
__device__ __forceinline__ void ldm_x4(uint32_t* r, uint32_t addr) {
    asm volatile("ldmatrix.sync.aligned.m8n8.x4.shared.b16 {%0,%1,%2,%3}, [%4];"
        : "=r"(r[0]), "=r"(r[1]), "=r"(r[2]), "=r"(r[3]) : "r"(addr));
}
__device__ __forceinline__ void mma16816(float* d, const uint32_t* a, const uint32_t* b) {
    asm volatile(
        "mma.sync.aligned.m16n8k16.row.col.f32.bf16.bf16.f32 "
        "{%0,%1,%2,%3}, {%4,%5,%6,%7}, {%8,%9}, {%0,%1,%2,%3};"
        : "+f"(d[0]), "+f"(d[1]), "+f"(d[2]), "+f"(d[3])
        : "r"(a[0]), "r"(a[1]), "r"(a[2]), "r"(a[3]), "r"(b[0]), "r"(b[1]));
}
__device__ __forceinline__ void cpasync16(uint32_t dst, const void* src) {
    asm volatile("cp.async.cg.shared.global [%0], [%1], 16;" :: "r"(dst), "l"(src));
}
#define CP_COMMIT() asm volatile("cp.async.commit_group;" ::: "memory")
#define CP_WAIT2()  asm volatile("cp.async.wait_group 2;" ::: "memory")
#define CP_WAIT1()  asm volatile("cp.async.wait_group 1;" ::: "memory")
#define CP_WAIT0()  asm volatile("cp.async.wait_group 0;" ::: "memory")

// ---------------------------------------------------------------------------
// K0a: split obs fp32 -> bf16 hi/lo
// ---------------------------------------------------------------------------
__global__ __launch_bounds__(256) void k0_split_A(const float4* __restrict__ obs4) {
    size_t i = (size_t)blockIdx.x * 256 + threadIdx.x;
    float4 v = obs4[i];
    size_t b = i * 4;
    __nv_bfloat16 h0 = __float2bfloat16(v.x);
    __nv_bfloat16 h1 = __float2bfloat16(v.y);
    __nv_bfloat16 h2 = __float2bfloat16(v.z);
    __nv_bfloat16 h3 = __float2bfloat16(v.w);
    __nv_bfloat16 l0 = __float2bfloat16(v.x - __bfloat162float(h0));
    __nv_bfloat16 l1 = __float2bfloat16(v.y - __bfloat162float(h1));
    __nv_bfloat16 l2 = __float2bfloat16(v.z - __bfloat162float(h2));
    __nv_bfloat16 l3 = __float2bfloat16(v.w - __bfloat162float(h3));
    *(__nv_bfloat162*)&g_Ah[b]     = __halves2bfloat162(h0, h1);
    *(__nv_bfloat162*)&g_Ah[b + 2] = __halves2bfloat162(h2, h3);
    *(__nv_bfloat162*)&g_Al[b]     = __halves2bfloat162(l0, l1);
    *(__nv_bfloat162*)&g_Al[b + 2] = __halves2bfloat162(l2, l3);
}

// K0b: pack embed weights [640][256] = [local(512); inter(64); intra(64)] + bias
__global__ __launch_bounds__(256) void k0_split_W(
    const float* __restrict__ lw, const float* __restrict__ lb,
    const float* __restrict__ iw, const float* __restrict__ ib,
    const float* __restrict__ tw, const float* __restrict__ tb)
{
    int row = blockIdx.x, col = threadIdx.x;
    const float* src; const float* bs; int r;
    if (row < 512)      { src = lw; bs = lb; r = row; }
    else if (row < 576) { src = iw; bs = ib; r = row - 512; }
    else                { src = tw; bs = tb; r = row - 576; }
    float x = src[r * OBSD + col];
    __nv_bfloat16 h = __float2bfloat16(x);
    g_Wh[row * OBSD + col] = h;
    g_Wl[row * OBSD + col] = __float2bfloat16(x - __bfloat162float(h));
    if (col == 0) g_bias[row] = bs[r];
}

// K0c: pack intra in-proj weights [384][64] (mu 0..191, std 192..383) + bias
__global__ __launch_bounds__(64) void k0_split_Wq(
    const float* __restrict__ wmi, const float* __restrict__ bmi,
    const float* __restrict__ wsi, const float* __restrict__ bsi)
{
    int row = blockIdx.x, col = threadIdx.x;
    const float* src; const float* bs; int r;
    if (row < 192) { src = wmi; bs = bmi; r = row; }
    else           { src = wsi; bs = bsi; r = row - 192; }
    float x = src[r * 64 + col];
    __nv_bfloat16 h = __float2bfloat16(x);
    g_Wqh[row * 64 + col] = h;
    g_Wql[row * 64 + col] = __float2bfloat16(x - __bfloat162float(h));
    if (col == 0) g_qbias[row] = bs[r];
}

// ---------------------------------------------------------------------------
// K1: mma.sync bf16-split GEMM  C[65536,640] = tanh(A @ W^T + b).
// grid (512, 10), block 256 (8 warps = 4M x 2N), launch_bounds(256,2).
// Tile M=128, N=64. 8 K-chunks of 32, 4-stage cp.async pipeline,
// SINGLE barrier per chunk (stage-after-barrier is WAR-safe at depth>=3).
// nb 0..7 -> out_ac, nb==8 -> g_inter_emb fp32, nb==9 -> g_Eh/g_El bf16 split.
// ---------------------------------------------------------------------------
#define K1_AH 0
#define K1_AL 8192
#define K1_BH 16384
#define K1_BL 20480
#define K1_BUF 24576
#define K1_SMEM (4 * K1_BUF)

__global__ __launch_bounds__(256, 2) void k1_mma(float* __restrict__ out_ac)
{
    extern __shared__ char sm1[];
    uint32_t smb = smem_u32(sm1);
    int t = threadIdx.x;
    int lane = t & 31, wid = t >> 5;
    int mwarp = wid & 3, nwarp = wid >> 2;
    int row0 = blockIdx.x * 128;
    int nb = blockIdx.y;
    int cb = nb * 64;

    int arow = t >> 1, aseg = (t & 1) * 2;   // A: 128 rows, 2 thr/row x 2 chunks(16B)
    int brow = t >> 2, bseg = t & 3;         // B: 64 rows, 4 thr/row x 1 chunk

    uint32_t a_row_im = (uint32_t)(mwarp * 32 + (lane & 15));
    uint32_t a_kb_im  = (uint32_t)((lane >> 4) * 16);
    uint32_t b_row_im = (uint32_t)(nwarp * 32 + ((lane >> 4) & 1) * 8 + (lane & 7));
    uint32_t b_kb_im  = (uint32_t)(((lane >> 3) & 1) * 16);

    auto stage = [&](int buf, int ck) {
        int k0 = ck * 32;
        uint32_t base = smb + buf * K1_BUF;
        size_t aoff = (size_t)(row0 + arow) * OBSD + k0 + aseg * 8;
        #pragma unroll
        for (int i = 0; i < 2; i++) {
            uint32_t so = swz64((uint32_t)arow * 64 + (aseg + i) * 16);
            cpasync16(base + K1_AH + so, &g_Ah[aoff + i * 8]);
            cpasync16(base + K1_AL + so, &g_Al[aoff + i * 8]);
        }
        size_t boff = (size_t)(cb + brow) * OBSD + k0 + bseg * 8;
        uint32_t so = swz64((uint32_t)brow * 64 + bseg * 16);
        cpasync16(base + K1_BH + so, &g_Wh[boff]);
        cpasync16(base + K1_BL + so, &g_Wl[boff]);
    };

    float acc[2][4][4];
    #pragma unroll
    for (int mt = 0; mt < 2; mt++)
        #pragma unroll
        for (int nt = 0; nt < 4; nt++)
            #pragma unroll
            for (int e = 0; e < 4; e++) acc[mt][nt][e] = 0.f;

    stage(0, 0);
    CP_COMMIT();
    stage(1, 1);
    CP_COMMIT();
    stage(2, 2);
    CP_COMMIT();

    for (int ck = 0; ck < 8; ck++) {
        int buf = ck & 3;
        if (ck + 2 < 8)      { CP_WAIT2(); }
        else if (ck + 1 < 8) { CP_WAIT1(); }
        else                 { CP_WAIT0(); }
        __syncthreads();     // chunk ck visible to all; all warps past compute(ck-1)
        if (ck + 3 < 8) {
            stage((ck + 3) & 3, ck + 3);   // overwrites buf (ck-1)&3 -> safe post-barrier
            CP_COMMIT();
        }

        uint32_t base = smb + buf * K1_BUF;
        #pragma unroll
        for (int ks = 0; ks < 2; ks++) {
            uint32_t aH[2][4], aL[2][4];
            #pragma unroll
            for (int mt = 0; mt < 2; mt++) {
                uint32_t off = swz64((a_row_im + mt * 16) * 64 + ks * 32 + a_kb_im);
                ldm_x4(aH[mt], base + K1_AH + off);
                ldm_x4(aL[mt], base + K1_AL + off);
            }
            uint32_t bH[2][4], bL[2][4];
            #pragma unroll
            for (int np = 0; np < 2; np++) {
                uint32_t off = swz64((b_row_im + np * 16) * 64 + ks * 32 + b_kb_im);
                ldm_x4(bH[np], base + K1_BH + off);
                ldm_x4(bL[np], base + K1_BL + off);
            }
            #pragma unroll
            for (int mt = 0; mt < 2; mt++)
                #pragma unroll
                for (int np = 0; np < 2; np++) {
                    mma16816(acc[mt][np * 2 + 0], aH[mt], bH[np] + 0);
                    mma16816(acc[mt][np * 2 + 1], aH[mt], bH[np] + 2);
                    mma16816(acc[mt][np * 2 + 0], aH[mt], bL[np] + 0);
                    mma16816(acc[mt][np * 2 + 1], aH[mt], bL[np] + 2);
                    mma16816(acc[mt][np * 2 + 0], aL[mt], bH[np] + 0);
                    mma16816(acc[mt][np * 2 + 1], aL[mt], bH[np] + 2);
                }
        }
    }

    // epilogue: bias + tanh
    #pragma unroll
    for (int mt = 0; mt < 2; mt++) {
        int rbase = row0 + mwarp * 32 + mt * 16 + (lane >> 2);
        #pragma unroll
        for (int nt = 0; nt < 4; nt++) {
            int colT = nwarp * 32 + nt * 8 + (lane & 3) * 2;
            float2 b2 = *(const float2*)&g_bias[cb + colT];
            #pragma unroll
            for (int rh = 0; rh < 2; rh++) {
                int row = rbase + rh * 8;
                float2 o;
                o.x = ftanh(acc[mt][nt][rh * 2 + 0] + b2.x);
                o.y = ftanh(acc[mt][nt][rh * 2 + 1] + b2.y);
                if (nb < 8) {
                    *(float2*)&out_ac[(size_t)row * 640 + cb + colT] = o;
                } else if (nb == 8) {
                    *(float2*)&g_inter_emb[(size_t)row * 64 + colT] = o;
                } else {
                    __nv_bfloat16 h0 = __float2bfloat16(o.x);
                    __nv_bfloat16 h1 = __float2bfloat16(o.y);
                    __nv_bfloat16 l0 = __float2bfloat16(o.x - __bfloat162float(h0));
                    __nv_bfloat16 l1 = __float2bfloat16(o.y - __bfloat162float(h1));
                    *(__nv_bfloat162*)&g_Eh[(size_t)row * 64 + colT] = __halves2bfloat162(h0, h1);
                    *(__nv_bfloat162*)&g_El[(size_t)row * 64 + colT] = __halves2bfloat162(l0, l1);
                }
            }
        }
    }
}

// ---------------------------------------------------------------------------
// K2a: mma.sync bf16-split GEMM  QKV_all[65536,384] = E @ Wq^T + qbias.
// grid (512, 6), block 256 (8 warps = 4M x 2N), launch_bounds(256,2).
// Tile M=128, N=64, K=64 (single chunk), SW128.
// ---------------------------------------------------------------------------
#define K2A_AH 0
#define K2A_AL 16384
#define K2A_BH 32768
#define K2A_BL 40960
#define K2A_SMEM 49152

__global__ __launch_bounds__(256, 2) void k2a_qkv_gemm()
{
    extern __shared__ char sm2[];
    uint32_t smb = smem_u32(sm2);
    int t = threadIdx.x;
    int lane = t & 31, wid = t >> 5;
    int mwarp = wid & 3, nwarp = wid >> 2;
    int row0 = blockIdx.x * 128;
    int cb = blockIdx.y * 64;

    uint32_t a_row_im = (uint32_t)(mwarp * 32 + (lane & 15));
    uint32_t a_kb_im  = (uint32_t)((lane >> 4) * 16);
    uint32_t b_row_im = (uint32_t)(nwarp * 32 + ((lane >> 4) & 1) * 8 + (lane & 7));
    uint32_t b_kb_im  = (uint32_t)(((lane >> 3) & 1) * 16);

    {
        int arow = t >> 1, akseg = t & 1;
        size_t aoff = (size_t)(row0 + arow) * 64 + akseg * 32;
        #pragma unroll
        for (int i = 0; i < 4; i++) {
            uint32_t so = swz128((uint32_t)arow * 128 + akseg * 64 + i * 16);
            cpasync16(smb + K2A_AH + so, &g_Eh[aoff + i * 8]);
            cpasync16(smb + K2A_AL + so, &g_El[aoff + i * 8]);
        }
        int brow = t >> 2, bkseg = t & 3;
        size_t boff = (size_t)(cb + brow) * 64 + bkseg * 16;
        #pragma unroll
        for (int i = 0; i < 2; i++) {
            uint32_t so = swz128((uint32_t)brow * 128 + bkseg * 32 + i * 16);
            cpasync16(smb + K2A_BH + so, &g_Wqh[boff + i * 8]);
            cpasync16(smb + K2A_BL + so, &g_Wql[boff + i * 8]);
        }
    }
    CP_COMMIT();
    CP_WAIT0();
    __syncthreads();

    float acc[2][4][4];
    #pragma unroll
    for (int mt = 0; mt < 2; mt++)
        #pragma unroll
        for (int nt = 0; nt < 4; nt++)
            #pragma unroll
            for (int e = 0; e < 4; e++) acc[mt][nt][e] = 0.f;

    #pragma unroll
    for (int ks = 0; ks < 4; ks++) {
        uint32_t aH[2][4], aL[2][4];
        #pragma unroll
        for (int mt = 0; mt < 2; mt++) {
            uint32_t off = swz128((a_row_im + mt * 16) * 128 + ks * 32 + a_kb_im);
            ldm_x4(aH[mt], smb + K2A_AH + off);
            ldm_x4(aL[mt], smb + K2A_AL + off);
        }
        uint32_t bH[2][4], bL[2][4];
        #pragma unroll
        for (int np = 0; np < 2; np++) {
            uint32_t off = swz128((b_row_im + np * 16) * 128 + ks * 32 + b_kb_im);
            ldm_x4(bH[np], smb + K2A_BH + off);
            ldm_x4(bL[np], smb + K2A_BL + off);
        }
        #pragma unroll
        for (int mt = 0; mt < 2; mt++)
            #pragma unroll
            for (int np = 0; np < 2; np++) {
                mma16816(acc[mt][np * 2 + 0], aH[mt], bH[np] + 0);
                mma16816(acc[mt][np * 2 + 1], aH[mt], bH[np] + 2);
                mma16816(acc[mt][np * 2 + 0], aH[mt], bL[np] + 0);
                mma16816(acc[mt][np * 2 + 1], aH[mt], bL[np] + 2);
                mma16816(acc[mt][np * 2 + 0], aL[mt], bH[np] + 0);
                mma16816(acc[mt][np * 2 + 1], aL[mt], bH[np] + 2);
            }
    }

    #pragma unroll
    for (int mt = 0; mt < 2; mt++) {
        int rbase = row0 + mwarp * 32 + mt * 16 + (lane >> 2);
        #pragma unroll
        for (int nt = 0; nt < 4; nt++) {
            int colg = cb + nwarp * 32 + nt * 8 + (lane & 3) * 2;
            float2 b2 = *(const float2*)&g_qbias[colg];
            #pragma unroll
            for (int rh = 0; rh < 2; rh++) {
                int row = rbase + rh * 8;
                float2 o;
                o.x = acc[mt][nt][rh * 2 + 0] + b2.x;
                o.y = acc[mt][nt][rh * 2 + 1] + b2.y;
                *(float2*)&g_qkv_all[(size_t)row * 384 + colg] = o;
            }
        }
    }
}

// ---------------------------------------------------------------------------
// K3: softmax pooling per group. 1 block / group, 256 threads.
// ---------------------------------------------------------------------------
__global__ __launch_bounds__(256) void k3_pool(
    const int* __restrict__ sets,
    const float* __restrict__ aw, const float* __restrict__ ab)
{
    __shared__ float X[64][65];
    __shared__ float wgt[64];
    __shared__ int rows[64];
    __shared__ float wm[2], wsum[2];
    __shared__ float red[4][64];

    int t = threadIdx.x;
    int g = blockIdx.x;
    if (t < 64) rows[t] = sets[g * 64 + t];
    __syncthreads();
    {
        int l = t >> 2, c = (t & 3) * 16;
        const float* src = &g_inter_emb[(size_t)rows[l] * 64 + c];
        #pragma unroll
        for (int i = 0; i < 4; i++) {
            float4 v = *(const float4*)&src[i * 4];
            X[l][c + i * 4 + 0] = v.x;
            X[l][c + i * 4 + 1] = v.y;
            X[l][c + i * 4 + 2] = v.z;
            X[l][c + i * 4 + 3] = v.w;
        }
    }
    __syncthreads();

    float lg = 0.f, e = 0.f;
    if (t < 64) {
        lg = ab[0];
        #pragma unroll 8
        for (int k = 0; k < 64; k++) lg = fmaf(X[t][k], aw[k], lg);
        float m = lg;
        #pragma unroll
        for (int o = 16; o; o >>= 1) m = fmaxf(m, __shfl_xor_sync(0xffffffffu, m, o));
        if ((t & 31) == 0) wm[t >> 5] = m;
    }
    __syncthreads();
    if (t < 64) {
        float m = fmaxf(wm[0], wm[1]);
        e = __expf(lg - m);
        float s = e;
        #pragma unroll
        for (int o = 16; o; o >>= 1) s += __shfl_xor_sync(0xffffffffu, s, o);
        if ((t & 31) == 0) wsum[t >> 5] = s;
    }
    __syncthreads();
    if (t < 64) wgt[t] = e / (wsum[0] + wsum[1]);
    __syncthreads();

    {
        int d = t & 63, seg = t >> 6;
        float acc = 0.f;
        #pragma unroll
        for (int k = seg * 16; k < seg * 16 + 16; k++)
            acc = fmaf(wgt[k], X[k][d], acc);
        red[seg][d] = acc;
    }
    __syncthreads();
    if (t < 64)
        g_pooled[g * 64 + t] = red[0][t] + red[1][t] + red[2][t] + red[3][t];
}

// ---------------------------------------------------------------------------
// K4a: inter QKV = pooled @ w_in^T + b.  grid (16, 2[mu/std]), 256 thr.
// ---------------------------------------------------------------------------
__global__ __launch_bounds__(256) void k4a_qkv(
    const float* __restrict__ wmi, const float* __restrict__ bmi,
    const float* __restrict__ wsi, const float* __restrict__ bsi)
{
    __shared__ float X[64][65];
    int t = threadIdx.x;
    int r0 = blockIdx.x * 64;
    int p = blockIdx.y;
    const float* Wi = p ? wsi : wmi;
    const float* bi = p ? bsi : bmi;

    {
        int l = t >> 2, c = (t & 3) * 16;
        #pragma unroll
        for (int i = 0; i < 4; i++) {
            float4 v = *(const float4*)&g_pooled[(r0 + l) * 64 + c + i * 4];
            X[l][c + i * 4 + 0] = v.x;
            X[l][c + i * 4 + 1] = v.y;
            X[l][c + i * 4 + 2] = v.z;
            X[l][c + i * 4 + 3] = v.w;
        }
    }
    __syncthreads();

    int l  = t & 63;
    int jb = t >> 6;
    for (int jj = 0; jj < 48; jj++) {
        int j = jb * 48 + jj;
        float acc = bi[j];
        #pragma unroll 8
        for (int k = 0; k < 64; k++) acc = fmaf(X[l][k], __ldg(&Wi[j * 64 + k]), acc);
        g_qkv[p][(r0 + l) * 192 + j] = acc;
    }
}

// ---------------------------------------------------------------------------
// K4b: inter attention (L=1024, dh=16). grid (16 qtiles, 4 heads, 2 passes),
// 512 threads: 8 key-chunks of 128 keys, partial online softmax + combine.
// ---------------------------------------------------------------------------
__global__ __launch_bounds__(512) void k4b_attn()
{
    extern __shared__ float sm4b[];
    float* Ks   = sm4b;
    float* Vs   = Ks + 1024 * 16;
    float* pm   = Vs + 1024 * 16;
    float* ps   = pm + 8 * 64;
    float* pacc = ps + 8 * 64;

    int t  = threadIdx.x;
    int kc = t >> 6, qi = t & 63;
    int q0 = blockIdx.x * 64;
    int h  = blockIdx.y;
    int p  = blockIdx.z;
    const float* QKV = g_qkv[p];

    for (int r = t; r < 1024; r += 512) {
        #pragma unroll
        for (int i = 0; i < 4; i++) {
            *(float4*)&Ks[r * 16 + i * 4] =
                *(const float4*)&QKV[(size_t)r * 192 + 64 + h * 16 + i * 4];
            *(float4*)&Vs[r * 16 + i * 4] =
                *(const float4*)&QKV[(size_t)r * 192 + 128 + h * 16 + i * 4];
        }
    }
    __syncthreads();

    float4 q[4];
    #pragma unroll
    for (int i = 0; i < 4; i++)
        q[i] = *(const float4*)&QKV[(size_t)(q0 + qi) * 192 + h * 16 + i * 4];

    float m = -1e30f, ssum = 0.f, acc[16];
    #pragma unroll
    for (int i = 0; i < 16; i++) acc[i] = 0.f;

    int jbase = kc * 128;
    for (int j = jbase; j < jbase + 128; j++) {
        const float4* kr = (const float4*)&Ks[j * 16];
        float4 k0 = kr[0], k1 = kr[1], k2 = kr[2], k3 = kr[3];
        float s = q[0].x * k0.x;
        s = fmaf(q[0].y, k0.y, s); s = fmaf(q[0].z, k0.z, s); s = fmaf(q[0].w, k0.w, s);
        s = fmaf(q[1].x, k1.x, s); s = fmaf(q[1].y, k1.y, s);
        s = fmaf(q[1].z, k1.z, s); s = fmaf(q[1].w, k1.w, s);
        s = fmaf(q[2].x, k2.x, s); s = fmaf(q[2].y, k2.y, s);
        s = fmaf(q[2].z, k2.z, s); s = fmaf(q[2].w, k2.w, s);
        s = fmaf(q[3].x, k3.x, s); s = fmaf(q[3].y, k3.y, s);
        s = fmaf(q[3].z, k3.z, s); s = fmaf(q[3].w, k3.w, s);
        s *= 0.25f;
        const float4* vr = (const float4*)&Vs[j * 16];
        float4 v0 = vr[0], v1 = vr[1], v2 = vr[2], v3 = vr[3];
        float vv[16] = {v0.x, v0.y, v0.z, v0.w, v1.x, v1.y, v1.z, v1.w,
                        v2.x, v2.y, v2.z, v2.w, v3.x, v3.y, v3.z, v3.w};
        if (s <= m) {
            float w = __expf(s - m);
            ssum += w;
            #pragma unroll
            for (int c = 0; c < 16; c++) acc[c] = fmaf(w, vv[c], acc[c]);
        } else {
            float corr = __expf(m - s);
            ssum = fmaf(ssum, corr, 1.f);
            #pragma unroll
            for (int c = 0; c < 16; c++) acc[c] = fmaf(acc[c], corr, vv[c]);
            m = s;
        }
    }
    pm[kc * 64 + qi] = m;
    ps[kc * 64 + qi] = ssum;
    #pragma unroll
    for (int c = 0; c < 16; c++) pacc[(kc * 64 + qi) * 16 + c] = acc[c];
    __syncthreads();

    if (t < 64) {
        float gm = -1e30f;
        #pragma unroll
        for (int i = 0; i < 8; i++) gm = fmaxf(gm, pm[i * 64 + t]);
        float s = 0.f, o[16];
        #pragma unroll
        for (int c = 0; c < 16; c++) o[c] = 0.f;
        #pragma unroll
        for (int i = 0; i < 8; i++) {
            float w = __expf(pm[i * 64 + t] - gm);
            s = fmaf(ps[i * 64 + t], w, s);
            #pragma unroll
            for (int c = 0; c < 16; c++)
                o[c] = fmaf(pacc[(i * 64 + t) * 16 + c], w, o[c]);
        }
        float inv = __fdividef(1.f, s);
        #pragma unroll
        for (int c = 0; c < 16; c++)
            g_attno[p][(size_t)(q0 + t) * 64 + h * 16 + c] = o[c] * inv;
    }
}

// ---------------------------------------------------------------------------
// K4c: inter out-proj, softplus, sample. grid 16, 256 threads.
// ---------------------------------------------------------------------------
__global__ __launch_bounds__(256) void k4c_proj(
    const float* __restrict__ wmo, const float* __restrict__ bmo,
    const float* __restrict__ wso, const float* __restrict__ bso,
    const float* __restrict__ eps_inter)
{
    __shared__ float Om[64][65];
    __shared__ float Os[64][65];
    int t = threadIdx.x;
    int r0 = blockIdx.x * 64;
    {
        int l = t >> 2, c = (t & 3) * 16;
        for (int i = 0; i < 16; i++) {
            Om[l][c + i] = g_attno[0][(size_t)(r0 + l) * 64 + c + i];
            Os[l][c + i] = g_attno[1][(size_t)(r0 + l) * 64 + c + i];
        }
    }
    __syncthreads();

    int lb = t >> 4, db = t & 15;
    float am[4][4], as[4][4];
    #pragma unroll
    for (int i = 0; i < 4; i++)
        #pragma unroll
        for (int j = 0; j < 4; j++) { am[i][j] = 0.f; as[i][j] = 0.f; }

    #pragma unroll 4
    for (int k = 0; k < 64; k++) {
        float om[4], os[4], wmv[4], wsv[4];
        #pragma unroll
        for (int i = 0; i < 4; i++) { om[i] = Om[lb * 4 + i][k]; os[i] = Os[lb * 4 + i][k]; }
        #pragma unroll
        for (int j = 0; j < 4; j++) {
            wmv[j] = __ldg(&wmo[(db * 4 + j) * 64 + k]);
            wsv[j] = __ldg(&wso[(db * 4 + j) * 64 + k]);
        }
        #pragma unroll
        for (int i = 0; i < 4; i++)
            #pragma unroll
            for (int j = 0; j < 4; j++) {
                am[i][j] = fmaf(om[i], wmv[j], am[i][j]);
                as[i][j] = fmaf(os[i], wsv[j], as[i][j]);
            }
    }
    #pragma unroll
    for (int i = 0; i < 4; i++) {
        int gi = r0 + lb * 4 + i;
        #pragma unroll
        for (int j = 0; j < 4; j++) {
            int d = db * 4 + j;
            float mu  = am[i][j] + bmo[d];
            float st  = softplusf(as[i][j] + bso[d] - 5.f);
            g_inter_mu[gi * 64 + d] = mu;
            g_inter_std[gi * 64 + d] = st;
            g_inter_sample[gi * 64 + d] = fmaf(st, eps_inter[gi * 64 + d], mu);
        }
    }
}

// ---------------------------------------------------------------------------
// K2: intra attention per group (QKV precomputed by k2a), out-proj,
// fused with ALL final scatter writes. 1 block / group, 256 threads.
// O and Wo stored TRANSPOSED (stride 68) so the out-proj reads are LDS.128.
// ---------------------------------------------------------------------------
__global__ __launch_bounds__(256) void k2_intra(
    const int* __restrict__ sets,
    const float* __restrict__ wmo, const float* __restrict__ bmo,
    const float* __restrict__ wso, const float* __restrict__ bso,
    const float* __restrict__ eps_intra,
    float* __restrict__ out_ac, float* __restrict__ out_mu, float* __restrict__ out_std)
{
    extern __shared__ float sm[];
    float* QKV  = sm;                    // [64][196]
    float* OT   = QKV + 64 * 196;        // [64 k][68]: OT[c*68 + query]
    float* WoT  = OT + 64 * 68;          // [64 k][68]: WoT[k*68 + outdim]
    float* bout = WoT + 64 * 68;         // [64]
    float* MUb  = bout + 64;             // [64][64]
    int*   rows = (int*)(MUb + 64 * 64); // [64]

    int t = threadIdx.x;
    int g = blockIdx.x;
    if (t < 64) rows[t] = sets[g * 64 + t];
    __syncthreads();

    for (int p = 0; p < 2; p++) {
        const float* wOut = p ? wso : wmo;
        const float* bOut = p ? bso : bmo;
        __syncthreads();
        // load out-proj weights TRANSPOSED: WoT[k][j] = wOut[j*64+k]
        for (int v = t; v < 1024; v += 256) {
            int j = v >> 4; int cv = (v & 15) * 4;
            float4 w4 = *(const float4*)&wOut[j * 64 + cv];
            WoT[(cv + 0) * 68 + j] = w4.x;
            WoT[(cv + 1) * 68 + j] = w4.y;
            WoT[(cv + 2) * 68 + j] = w4.z;
            WoT[(cv + 3) * 68 + j] = w4.w;
        }
        if (t < 64) bout[t] = bOut[t];
        {
            int l = t >> 2, q4 = t & 3;
            const float* src = &g_qkv_all[(size_t)rows[l] * 384 + p * 192 + q4 * 48];
            float* dst = &QKV[l * 196 + q4 * 48];
            #pragma unroll
            for (int i = 0; i < 12; i++)
                *(float4*)&dst[i * 4] = *(const float4*)&src[i * 4];
        }
        __syncthreads();

        // attention: thread = (query i, head h), online softmax (branch form)
        {
            int i = t & 63, h = t >> 6;
            float4 q[4];
            #pragma unroll
            for (int c = 0; c < 4; c++)
                q[c] = *(const float4*)&QKV[i * 196 + h * 16 + c * 4];
            float m = -1e30f, ssum = 0.f, acc[16];
            #pragma unroll
            for (int c = 0; c < 16; c++) acc[c] = 0.f;
            for (int j = 0; j < 64; j++) {
                const float4* kr = (const float4*)&QKV[j * 196 + 64 + h * 16];
                float4 k0 = kr[0], k1 = kr[1], k2 = kr[2], k3 = kr[3];
                float s = q[0].x * k0.x;
                s = fmaf(q[0].y, k0.y, s); s = fmaf(q[0].z, k0.z, s); s = fmaf(q[0].w, k0.w, s);
                s = fmaf(q[1].x, k1.x, s); s = fmaf(q[1].y, k1.y, s);
                s = fmaf(q[1].z, k1.z, s); s = fmaf(q[1].w, k1.w, s);
                s = fmaf(q[2].x, k2.x, s); s = fmaf(q[2].y, k2.y, s);
                s = fmaf(q[2].z, k2.z, s); s = fmaf(q[2].w, k2.w, s);
                s = fmaf(q[3].x, k3.x, s); s = fmaf(q[3].y, k3.y, s);
                s = fmaf(q[3].z, k3.z, s); s = fmaf(q[3].w, k3.w, s);
                s *= 0.25f;
                const float4* vr = (const float4*)&QKV[j * 196 + 128 + h * 16];
                float4 v0 = vr[0], v1 = vr[1], v2 = vr[2], v3 = vr[3];
                float vv[16] = {v0.x, v0.y, v0.z, v0.w, v1.x, v1.y, v1.z, v1.w,
                                v2.x, v2.y, v2.z, v2.w, v3.x, v3.y, v3.z, v3.w};
                if (s <= m) {
                    float w = __expf(s - m);
                    ssum += w;
                    #pragma unroll
                    for (int c = 0; c < 16; c++) acc[c] = fmaf(w, vv[c], acc[c]);
                } else {
                    float corr = __expf(m - s);
                    ssum = fmaf(ssum, corr, 1.f);
                    #pragma unroll
                    for (int c = 0; c < 16; c++) acc[c] = fmaf(acc[c], corr, vv[c]);
                    m = s;
                }
            }
            float inv = __fdividef(1.f, ssum);
            // store TRANSPOSED: OT[(h*16+c)][i]
            #pragma unroll
            for (int c = 0; c < 16; c++) OT[(h * 16 + c) * 68 + i] = acc[c] * inv;
        }
        __syncthreads();

        // out proj via LDS.128: acc[i][j] += OT[k][lb*4+i] * WoT[k][db*4+j]
        {
            int lb = t >> 4, db = t & 15;
            float acc[4][4];
            #pragma unroll
            for (int i = 0; i < 4; i++)
                #pragma unroll
                for (int j = 0; j < 4; j++) acc[i][j] = 0.f;
            #pragma unroll 8
            for (int k = 0; k < 64; k++) {
                float4 ov = *(const float4*)&OT[k * 68 + lb * 4];
                float4 wv = *(const float4*)&WoT[k * 68 + db * 4];
                float ovv[4] = {ov.x, ov.y, ov.z, ov.w};
                float wvv[4] = {wv.x, wv.y, wv.z, wv.w};
                #pragma unroll
                for (int i = 0; i < 4; i++)
                    #pragma unroll
                    for (int j = 0; j < 4; j++)
                        acc[i][j] = fmaf(ovv[i], wvv[j], acc[i][j]);
            }
            int d0 = db * 4;
            #pragma unroll
            for (int i = 0; i < 4; i++) {
                int l = lb * 4 + i;
                int row = rows[l];
                float4 v;
                v.x = acc[i][0] + bout[d0 + 0];
                v.y = acc[i][1] + bout[d0 + 1];
                v.z = acc[i][2] + bout[d0 + 2];
                v.w = acc[i][3] + bout[d0 + 3];
                if (p == 0) {
                    *(float4*)&MUb[l * 64 + d0] = v;
                    *(float4*)&out_mu[(size_t)row * 128 + d0] = v;
                    *(float4*)&out_mu[(size_t)row * 128 + 64 + d0] =
                        *(const float4*)&g_inter_mu[g * 64 + d0];
                    *(float4*)&out_ac[(size_t)row * 640 + 512 + d0] =
                        *(const float4*)&g_inter_sample[g * 64 + d0];
                } else {
                    float4 st;
                    st.x = softplusf(v.x - 5.f);
                    st.y = softplusf(v.y - 5.f);
                    st.z = softplusf(v.z - 5.f);
                    st.w = softplusf(v.w - 5.f);
                    float4 mu4 = *(const float4*)&MUb[l * 64 + d0];
                    float4 ep  = *(const float4*)&eps_intra[(size_t)row * 64 + d0];
                    float4 samp;
                    samp.x = fmaf(st.x, ep.x, mu4.x);
                    samp.y = fmaf(st.y, ep.y, mu4.y);
                    samp.z = fmaf(st.z, ep.z, mu4.z);
                    samp.w = fmaf(st.w, ep.w, mu4.w);
                    *(float4*)&out_std[(size_t)row * 128 + d0] = st;
                    *(float4*)&out_std[(size_t)row * 128 + 64 + d0] =
                        *(const float4*)&g_inter_std[g * 64 + d0];
                    *(float4*)&out_ac[(size_t)row * 640 + 576 + d0] = samp;
                }
            }
        }
    }
}

// ---------------------------------------------------------------------------
extern "C" void kernel_launch(void* const* d_in, const int* in_sizes, int n_in,
                              void* d_out, int out_size)
{
    (void)in_sizes; (void)n_in; (void)out_size;
    const float* obs        = (const float*)d_in[0];
    const int*   sets       = (const int*)  d_in[1];
    const float* eps_intra  = (const float*)d_in[2];
    const float* eps_inter  = (const float*)d_in[3];
    const float* local_w    = (const float*)d_in[4];
    const float* local_b    = (const float*)d_in[5];
    const float* inter_emb_w= (const float*)d_in[6];
    const float* inter_emb_b= (const float*)d_in[7];
    const float* intra_emb_w= (const float*)d_in[8];
    const float* intra_emb_b= (const float*)d_in[9];
    const float* amu_in_w   = (const float*)d_in[10];
    const float* amu_in_b   = (const float*)d_in[11];
    const float* amu_out_w  = (const float*)d_in[12];
    const float* amu_out_b  = (const float*)d_in[13];
    const float* astd_in_w  = (const float*)d_in[14];
    const float* astd_in_b  = (const float*)d_in[15];
    const float* astd_out_w = (const float*)d_in[16];
    const float* astd_out_b = (const float*)d_in[17];
    const float* emu_in_w   = (const float*)d_in[18];
    const float* emu_in_b   = (const float*)d_in[19];
    const float* emu_out_w  = (const float*)d_in[20];
    const float* emu_out_b  = (const float*)d_in[21];
    const float* estd_in_w  = (const float*)d_in[22];
    const float* estd_in_b  = (const float*)d_in[23];
    const float* estd_out_w = (const float*)d_in[24];
    const float* estd_out_b = (const float*)d_in[25];
    const float* attset_w   = (const float*)d_in[26];
    const float* attset_b   = (const float*)d_in[27];

    float* out_ac  = (float*)d_out;
    float* out_mu  = out_ac + (size_t)NN * 640;
    float* out_std = out_mu + (size_t)NN * 128;

    const int k2_smem  = (64*196 + 64*68 + 64*68 + 64 + 64*64) * 4 + 64 * 4;
    const int k4b_smem = (2 * 1024 * 16 + 8 * 64 * 2 + 8 * 64 * 16) * 4;
    cudaFuncSetAttribute(k2_intra, cudaFuncAttributeMaxDynamicSharedMemorySize, k2_smem);
    cudaFuncSetAttribute(k4b_attn, cudaFuncAttributeMaxDynamicSharedMemorySize, k4b_smem);
    cudaFuncSetAttribute(k1_mma, cudaFuncAttributeMaxDynamicSharedMemorySize, K1_SMEM);
    cudaFuncSetAttribute(k2a_qkv_gemm, cudaFuncAttributeMaxDynamicSharedMemorySize, K2A_SMEM);

    // split inputs into bf16 hi/lo
    k0_split_A<<<(NN * OBSD / 4 + 255) / 256, 256>>>((const float4*)obs);
    k0_split_W<<<640, 256>>>(local_w, local_b, inter_emb_w, inter_emb_b,
                             intra_emb_w, intra_emb_b);
    k0_split_Wq<<<384, 64>>>(amu_in_w, amu_in_b, astd_in_w, astd_in_b);

    dim3 g1(512, 10);
    k1_mma<<<g1, 256, K1_SMEM>>>(out_ac);
    dim3 g2a(512, 6);
    k2a_qkv_gemm<<<g2a, 256, K2A_SMEM>>>();

    k3_pool<<<GG, 256>>>(sets, attset_w, attset_b);
    dim3 g4a(16, 2);
    k4a_qkv<<<g4a, 256>>>(emu_in_w, emu_in_b, estd_in_w, estd_in_b);
    dim3 g4b(16, 4, 2);
    k4b_attn<<<g4b, 512, k4b_smem>>>();
    k4c_proj<<<16, 256>>>(emu_out_w, emu_out_b, estd_out_w, estd_out_b, eps_inter);
    k2_intra<<<GG, 256, k2_smem>>>(sets,
                                   amu_out_w, amu_out_b, astd_out_w, astd_out_b,
                                   eps_intra, out_ac, out_mu, out_std);
}

// round 15
// speedup vs baseline: 1.0221x; 1.0221x over previous
#include <cuda_runtime.h>
#include <cuda_bf16.h>
#include <math.h>
#include <stdint.h>

#define NN 65536
#define GG 1024
#define SSZ 64
#define DD 64
#define OBSD 256
#define HIDD 512

// ---------------- scratch (device globals; no allocations allowed) ----------
__device__ __align__(16) float g_inter_emb[NN * DD];
__device__ __align__(16) float g_pooled[GG * DD];
__device__ __align__(16) float g_qkv[2][GG * 3 * DD];
__device__ __align__(16) float g_attno[2][GG * DD];
__device__ __align__(16) float g_inter_mu[GG * DD];
__device__ __align__(16) float g_inter_std[GG * DD];
__device__ __align__(16) float g_inter_sample[GG * DD];

// bf16 hi/lo split operands
__device__ __align__(16) __nv_bfloat16 g_Ah[(size_t)NN * OBSD];
__device__ __align__(16) __nv_bfloat16 g_Al[(size_t)NN * OBSD];
__device__ __align__(16) __nv_bfloat16 g_Wh[640 * OBSD];
__device__ __align__(16) __nv_bfloat16 g_Wl[640 * OBSD];
__device__ float g_bias[640];

// intra_emb as bf16 hi/lo (input to k2a GEMM)
__device__ __align__(16) __nv_bfloat16 g_Eh[(size_t)NN * DD];
__device__ __align__(16) __nv_bfloat16 g_El[(size_t)NN * DD];
// packed intra in-proj weights [384=192mu+192std][64] hi/lo + bias
__device__ __align__(16) __nv_bfloat16 g_Wqh[384 * DD];
__device__ __align__(16) __nv_bfloat16 g_Wql[384 * DD];
__device__ float g_qbias[384];
// QKV (bias included) for all agents: [65536][384] (0..191 mu, 192..383 std)
__device__ __align__(16) float g_qkv_all[(size_t)NN * 384];

__device__ __forceinline__ float softplusf(float x) {
    return (x > 20.f) ? x : __logf(1.f + __expf(x));
}
__device__ __forceinline__ float ftanh(float x) {
    float ax = fabsf(x);
    float t = __expf(-2.f * ax);
    float r = __fdividef(1.f - t, 1.f + t);
    return copysignf(r, x);
}

__device__ __forceinline__ uint32_t smem_u32(const void* p) {
    uint32_t a;
    asm("{ .reg .u64 t; cvta.to.shared.u64 t, %1; cvt.u32.u64 %0, t; }" : "=r"(a) : "l"(p));
    return a;
}
__device__ __forceinline__ uint32_t swz128(uint32_t off) {
    return off ^ ((off >> 3) & 0x70);
}
__device__ __forceinline__ uint32_t swz64(uint32_t off) {
    return off ^ ((off >> 3) & 0x30);
}
__device__ __forceinline__ void ldm_x4(uint32_t* r, uint32_t addr) {
    asm volatile("ldmatrix.sync.aligned.m8n8.x4.shared.b16 {%0,%1,%2,%3}, [%4];"
        : "=r"(r[0]), "=r"(r[1]), "=r"(r[2]), "=r"(r[3]) : "r"(addr));
}
__device__ __forceinline__ void mma16816(float* d, const uint32_t* a, const uint32_t* b) {
    asm volatile(
        "mma.sync.aligned.m16n8k16.row.col.f32.bf16.bf16.f32 "
        "{%0,%1,%2,%3}, {%4,%5,%6,%7}, {%8,%9}, {%0,%1,%2,%3};"
        : "+f"(d[0]), "+f"(d[1]), "+f"(d[2]), "+f"(d[3])
        : "r"(a[0]), "r"(a[1]), "r"(a[2]), "r"(a[3]), "r"(b[0]), "r"(b[1]));
}
__device__ __forceinline__ void cpasync16(uint32_t dst, const void* src) {
    asm volatile("cp.async.cg.shared.global [%0], [%1], 16;" :: "r"(dst), "l"(src));
}
#define CP_COMMIT() asm volatile("cp.async.commit_group;" ::: "memory")
#define CP_WAIT2()  asm volatile("cp.async.wait_group 2;" ::: "memory")
#define CP_WAIT1()  asm volatile("cp.async.wait_group 1;" ::: "memory")
#define CP_WAIT0()  asm volatile("cp.async.wait_group 0;" ::: "memory")

// ---------------------------------------------------------------------------
// K0a: split obs fp32 -> bf16 hi/lo
// ---------------------------------------------------------------------------
__global__ __launch_bounds__(256) void k0_split_A(const float4* __restrict__ obs4) {
    size_t i = (size_t)blockIdx.x * 256 + threadIdx.x;
    float4 v = obs4[i];
    size_t b = i * 4;
    __nv_bfloat16 h0 = __float2bfloat16(v.x);
    __nv_bfloat16 h1 = __float2bfloat16(v.y);
    __nv_bfloat16 h2 = __float2bfloat16(v.z);
    __nv_bfloat16 h3 = __float2bfloat16(v.w);
    __nv_bfloat16 l0 = __float2bfloat16(v.x - __bfloat162float(h0));
    __nv_bfloat16 l1 = __float2bfloat16(v.y - __bfloat162float(h1));
    __nv_bfloat16 l2 = __float2bfloat16(v.z - __bfloat162float(h2));
    __nv_bfloat16 l3 = __float2bfloat16(v.w - __bfloat162float(h3));
    *(__nv_bfloat162*)&g_Ah[b]     = __halves2bfloat162(h0, h1);
    *(__nv_bfloat162*)&g_Ah[b + 2] = __halves2bfloat162(h2, h3);
    *(__nv_bfloat162*)&g_Al[b]     = __halves2bfloat162(l0, l1);
    *(__nv_bfloat162*)&g_Al[b + 2] = __halves2bfloat162(l2, l3);
}

// K0b: pack embed weights [640][256] = [local(512); inter(64); intra(64)] + bias
__global__ __launch_bounds__(256) void k0_split_W(
    const float* __restrict__ lw, const float* __restrict__ lb,
    const float* __restrict__ iw, const float* __restrict__ ib,
    const float* __restrict__ tw, const float* __restrict__ tb)
{
    int row = blockIdx.x, col = threadIdx.x;
    const float* src; const float* bs; int r;
    if (row < 512)      { src = lw; bs = lb; r = row; }
    else if (row < 576) { src = iw; bs = ib; r = row - 512; }
    else                { src = tw; bs = tb; r = row - 576; }
    float x = src[r * OBSD + col];
    __nv_bfloat16 h = __float2bfloat16(x);
    g_Wh[row * OBSD + col] = h;
    g_Wl[row * OBSD + col] = __float2bfloat16(x - __bfloat162float(h));
    if (col == 0) g_bias[row] = bs[r];
}

// K0c: pack intra in-proj weights [384][64] (mu 0..191, std 192..383) + bias
__global__ __launch_bounds__(64) void k0_split_Wq(
    const float* __restrict__ wmi, const float* __restrict__ bmi,
    const float* __restrict__ wsi, const float* __restrict__ bsi)
{
    int row = blockIdx.x, col = threadIdx.x;
    const float* src; const float* bs; int r;
    if (row < 192) { src = wmi; bs = bmi; r = row; }
    else           { src = wsi; bs = bsi; r = row - 192; }
    float x = src[r * 64 + col];
    __nv_bfloat16 h = __float2bfloat16(x);
    g_Wqh[row * 64 + col] = h;
    g_Wql[row * 64 + col] = __float2bfloat16(x - __bfloat162float(h));
    if (col == 0) g_qbias[row] = bs[r];
}

// ---------------------------------------------------------------------------
// K1: mma.sync bf16-split GEMM  C[65536,640] = tanh(A @ W^T + b).
// grid (512, 10), block 256 (8 warps = 4M x 2N), launch_bounds(256,2).
// Tile M=128, N=64. 8 K-chunks of 32, 3-stage cp.async pipeline, SW64 swizzle.
// (Round-13 measured-best variant: two barriers per chunk.)
// nb 0..7 -> out_ac, nb==8 -> g_inter_emb fp32, nb==9 -> g_Eh/g_El bf16 split.
// ---------------------------------------------------------------------------
#define K1_AH 0
#define K1_AL 8192
#define K1_BH 16384
#define K1_BL 20480
#define K1_BUF 24576
#define K1_SMEM (3 * K1_BUF)

__global__ __launch_bounds__(256, 2) void k1_mma(float* __restrict__ out_ac)
{
    extern __shared__ char sm1[];
    uint32_t smb = smem_u32(sm1);
    int t = threadIdx.x;
    int lane = t & 31, wid = t >> 5;
    int mwarp = wid & 3, nwarp = wid >> 2;
    int row0 = blockIdx.x * 128;
    int nb = blockIdx.y;
    int cb = nb * 64;

    int arow = t >> 1, aseg = (t & 1) * 2;   // A: 128 rows, 2 thr/row x 2 chunks(16B)
    int brow = t >> 2, bseg = t & 3;         // B: 64 rows, 4 thr/row x 1 chunk

    uint32_t a_row_im = (uint32_t)(mwarp * 32 + (lane & 15));
    uint32_t a_kb_im  = (uint32_t)((lane >> 4) * 16);
    uint32_t b_row_im = (uint32_t)(nwarp * 32 + ((lane >> 4) & 1) * 8 + (lane & 7));
    uint32_t b_kb_im  = (uint32_t)(((lane >> 3) & 1) * 16);

    auto stage = [&](int buf, int ck) {
        int k0 = ck * 32;
        uint32_t base = smb + buf * K1_BUF;
        size_t aoff = (size_t)(row0 + arow) * OBSD + k0 + aseg * 8;
        #pragma unroll
        for (int i = 0; i < 2; i++) {
            uint32_t so = swz64((uint32_t)arow * 64 + (aseg + i) * 16);
            cpasync16(base + K1_AH + so, &g_Ah[aoff + i * 8]);
            cpasync16(base + K1_AL + so, &g_Al[aoff + i * 8]);
        }
        size_t boff = (size_t)(cb + brow) * OBSD + k0 + bseg * 8;
        uint32_t so = swz64((uint32_t)brow * 64 + bseg * 16);
        cpasync16(base + K1_BH + so, &g_Wh[boff]);
        cpasync16(base + K1_BL + so, &g_Wl[boff]);
    };

    float acc[2][4][4];
    #pragma unroll
    for (int mt = 0; mt < 2; mt++)
        #pragma unroll
        for (int nt = 0; nt < 4; nt++)
            #pragma unroll
            for (int e = 0; e < 4; e++) acc[mt][nt][e] = 0.f;

    stage(0, 0);
    CP_COMMIT();
    stage(1, 1);
    CP_COMMIT();

    for (int ck = 0; ck < 8; ck++) {
        int buf = ck % 3;
        __syncthreads();           // all warps done computing chunk ck-1
        if (ck + 2 < 8) {
            stage((ck + 2) % 3, ck + 2);
            CP_COMMIT();
            CP_WAIT2();            // chunk ck complete
        } else if (ck + 1 < 8) {
            CP_WAIT1();
        } else {
            CP_WAIT0();
        }
        __syncthreads();           // staged data visible to all warps

        uint32_t base = smb + buf * K1_BUF;
        #pragma unroll
        for (int ks = 0; ks < 2; ks++) {
            uint32_t aH[2][4], aL[2][4];
            #pragma unroll
            for (int mt = 0; mt < 2; mt++) {
                uint32_t off = swz64((a_row_im + mt * 16) * 64 + ks * 32 + a_kb_im);
                ldm_x4(aH[mt], base + K1_AH + off);
                ldm_x4(aL[mt], base + K1_AL + off);
            }
            uint32_t bH[2][4], bL[2][4];
            #pragma unroll
            for (int np = 0; np < 2; np++) {
                uint32_t off = swz64((b_row_im + np * 16) * 64 + ks * 32 + b_kb_im);
                ldm_x4(bH[np], base + K1_BH + off);
                ldm_x4(bL[np], base + K1_BL + off);
            }
            #pragma unroll
            for (int mt = 0; mt < 2; mt++)
                #pragma unroll
                for (int np = 0; np < 2; np++) {
                    mma16816(acc[mt][np * 2 + 0], aH[mt], bH[np] + 0);
                    mma16816(acc[mt][np * 2 + 1], aH[mt], bH[np] + 2);
                    mma16816(acc[mt][np * 2 + 0], aH[mt], bL[np] + 0);
                    mma16816(acc[mt][np * 2 + 1], aH[mt], bL[np] + 2);
                    mma16816(acc[mt][np * 2 + 0], aL[mt], bH[np] + 0);
                    mma16816(acc[mt][np * 2 + 1], aL[mt], bH[np] + 2);
                }
        }
    }

    // epilogue: bias + tanh
    #pragma unroll
    for (int mt = 0; mt < 2; mt++) {
        int rbase = row0 + mwarp * 32 + mt * 16 + (lane >> 2);
        #pragma unroll
        for (int nt = 0; nt < 4; nt++) {
            int colT = nwarp * 32 + nt * 8 + (lane & 3) * 2;
            float2 b2 = *(const float2*)&g_bias[cb + colT];
            #pragma unroll
            for (int rh = 0; rh < 2; rh++) {
                int row = rbase + rh * 8;
                float2 o;
                o.x = ftanh(acc[mt][nt][rh * 2 + 0] + b2.x);
                o.y = ftanh(acc[mt][nt][rh * 2 + 1] + b2.y);
                if (nb < 8) {
                    *(float2*)&out_ac[(size_t)row * 640 + cb + colT] = o;
                } else if (nb == 8) {
                    *(float2*)&g_inter_emb[(size_t)row * 64 + colT] = o;
                } else {
                    __nv_bfloat16 h0 = __float2bfloat16(o.x);
                    __nv_bfloat16 h1 = __float2bfloat16(o.y);
                    __nv_bfloat16 l0 = __float2bfloat16(o.x - __bfloat162float(h0));
                    __nv_bfloat16 l1 = __float2bfloat16(o.y - __bfloat162float(h1));
                    *(__nv_bfloat162*)&g_Eh[(size_t)row * 64 + colT] = __halves2bfloat162(h0, h1);
                    *(__nv_bfloat162*)&g_El[(size_t)row * 64 + colT] = __halves2bfloat162(l0, l1);
                }
            }
        }
    }
}

// ---------------------------------------------------------------------------
// K2a: mma.sync bf16-split GEMM  QKV_all[65536,384] = E @ Wq^T + qbias.
// grid (512, 6), block 256 (8 warps = 4M x 2N), launch_bounds(256,2).
// Tile M=128, N=64, K=64 (single chunk), SW128.
// ---------------------------------------------------------------------------
#define K2A_AH 0
#define K2A_AL 16384
#define K2A_BH 32768
#define K2A_BL 40960
#define K2A_SMEM 49152

__global__ __launch_bounds__(256, 2) void k2a_qkv_gemm()
{
    extern __shared__ char sm2[];
    uint32_t smb = smem_u32(sm2);
    int t = threadIdx.x;
    int lane = t & 31, wid = t >> 5;
    int mwarp = wid & 3, nwarp = wid >> 2;
    int row0 = blockIdx.x * 128;
    int cb = blockIdx.y * 64;

    uint32_t a_row_im = (uint32_t)(mwarp * 32 + (lane & 15));
    uint32_t a_kb_im  = (uint32_t)((lane >> 4) * 16);
    uint32_t b_row_im = (uint32_t)(nwarp * 32 + ((lane >> 4) & 1) * 8 + (lane & 7));
    uint32_t b_kb_im  = (uint32_t)(((lane >> 3) & 1) * 16);

    {
        int arow = t >> 1, akseg = t & 1;
        size_t aoff = (size_t)(row0 + arow) * 64 + akseg * 32;
        #pragma unroll
        for (int i = 0; i < 4; i++) {
            uint32_t so = swz128((uint32_t)arow * 128 + akseg * 64 + i * 16);
            cpasync16(smb + K2A_AH + so, &g_Eh[aoff + i * 8]);
            cpasync16(smb + K2A_AL + so, &g_El[aoff + i * 8]);
        }
        int brow = t >> 2, bkseg = t & 3;
        size_t boff = (size_t)(cb + brow) * 64 + bkseg * 16;
        #pragma unroll
        for (int i = 0; i < 2; i++) {
            uint32_t so = swz128((uint32_t)brow * 128 + bkseg * 32 + i * 16);
            cpasync16(smb + K2A_BH + so, &g_Wqh[boff + i * 8]);
            cpasync16(smb + K2A_BL + so, &g_Wql[boff + i * 8]);
        }
    }
    CP_COMMIT();
    CP_WAIT0();
    __syncthreads();

    float acc[2][4][4];
    #pragma unroll
    for (int mt = 0; mt < 2; mt++)
        #pragma unroll
        for (int nt = 0; nt < 4; nt++)
            #pragma unroll
            for (int e = 0; e < 4; e++) acc[mt][nt][e] = 0.f;

    #pragma unroll
    for (int ks = 0; ks < 4; ks++) {
        uint32_t aH[2][4], aL[2][4];
        #pragma unroll
        for (int mt = 0; mt < 2; mt++) {
            uint32_t off = swz128((a_row_im + mt * 16) * 128 + ks * 32 + a_kb_im);
            ldm_x4(aH[mt], smb + K2A_AH + off);
            ldm_x4(aL[mt], smb + K2A_AL + off);
        }
        uint32_t bH[2][4], bL[2][4];
        #pragma unroll
        for (int np = 0; np < 2; np++) {
            uint32_t off = swz128((b_row_im + np * 16) * 128 + ks * 32 + b_kb_im);
            ldm_x4(bH[np], smb + K2A_BH + off);
            ldm_x4(bL[np], smb + K2A_BL + off);
        }
        #pragma unroll
        for (int mt = 0; mt < 2; mt++)
            #pragma unroll
            for (int np = 0; np < 2; np++) {
                mma16816(acc[mt][np * 2 + 0], aH[mt], bH[np] + 0);
                mma16816(acc[mt][np * 2 + 1], aH[mt], bH[np] + 2);
                mma16816(acc[mt][np * 2 + 0], aH[mt], bL[np] + 0);
                mma16816(acc[mt][np * 2 + 1], aH[mt], bL[np] + 2);
                mma16816(acc[mt][np * 2 + 0], aL[mt], bH[np] + 0);
                mma16816(acc[mt][np * 2 + 1], aL[mt], bH[np] + 2);
            }
    }

    #pragma unroll
    for (int mt = 0; mt < 2; mt++) {
        int rbase = row0 + mwarp * 32 + mt * 16 + (lane >> 2);
        #pragma unroll
        for (int nt = 0; nt < 4; nt++) {
            int colg = cb + nwarp * 32 + nt * 8 + (lane & 3) * 2;
            float2 b2 = *(const float2*)&g_qbias[colg];
            #pragma unroll
            for (int rh = 0; rh < 2; rh++) {
                int row = rbase + rh * 8;
                float2 o;
                o.x = acc[mt][nt][rh * 2 + 0] + b2.x;
                o.y = acc[mt][nt][rh * 2 + 1] + b2.y;
                *(float2*)&g_qkv_all[(size_t)row * 384 + colg] = o;
            }
        }
    }
}

// ---------------------------------------------------------------------------
// K3: softmax pooling per group. 1 block / group, 256 threads.
// ---------------------------------------------------------------------------
__global__ __launch_bounds__(256) void k3_pool(
    const int* __restrict__ sets,
    const float* __restrict__ aw, const float* __restrict__ ab)
{
    __shared__ float X[64][65];
    __shared__ float wgt[64];
    __shared__ int rows[64];
    __shared__ float wm[2], wsum[2];
    __shared__ float red[4][64];

    int t = threadIdx.x;
    int g = blockIdx.x;
    if (t < 64) rows[t] = sets[g * 64 + t];
    __syncthreads();
    {
        int l = t >> 2, c = (t & 3) * 16;
        const float* src = &g_inter_emb[(size_t)rows[l] * 64 + c];
        #pragma unroll
        for (int i = 0; i < 4; i++) {
            float4 v = *(const float4*)&src[i * 4];
            X[l][c + i * 4 + 0] = v.x;
            X[l][c + i * 4 + 1] = v.y;
            X[l][c + i * 4 + 2] = v.z;
            X[l][c + i * 4 + 3] = v.w;
        }
    }
    __syncthreads();

    float lg = 0.f, e = 0.f;
    if (t < 64) {
        lg = ab[0];
        #pragma unroll 8
        for (int k = 0; k < 64; k++) lg = fmaf(X[t][k], aw[k], lg);
        float m = lg;
        #pragma unroll
        for (int o = 16; o; o >>= 1) m = fmaxf(m, __shfl_xor_sync(0xffffffffu, m, o));
        if ((t & 31) == 0) wm[t >> 5] = m;
    }
    __syncthreads();
    if (t < 64) {
        float m = fmaxf(wm[0], wm[1]);
        e = __expf(lg - m);
        float s = e;
        #pragma unroll
        for (int o = 16; o; o >>= 1) s += __shfl_xor_sync(0xffffffffu, s, o);
        if ((t & 31) == 0) wsum[t >> 5] = s;
    }
    __syncthreads();
    if (t < 64) wgt[t] = e / (wsum[0] + wsum[1]);
    __syncthreads();

    {
        int d = t & 63, seg = t >> 6;
        float acc = 0.f;
        #pragma unroll
        for (int k = seg * 16; k < seg * 16 + 16; k++)
            acc = fmaf(wgt[k], X[k][d], acc);
        red[seg][d] = acc;
    }
    __syncthreads();
    if (t < 64)
        g_pooled[g * 64 + t] = red[0][t] + red[1][t] + red[2][t] + red[3][t];
}

// ---------------------------------------------------------------------------
// K4a: inter QKV = pooled @ w_in^T + b.  grid (16, 2[mu/std]), 256 thr.
// ---------------------------------------------------------------------------
__global__ __launch_bounds__(256) void k4a_qkv(
    const float* __restrict__ wmi, const float* __restrict__ bmi,
    const float* __restrict__ wsi, const float* __restrict__ bsi)
{
    __shared__ float X[64][65];
    int t = threadIdx.x;
    int r0 = blockIdx.x * 64;
    int p = blockIdx.y;
    const float* Wi = p ? wsi : wmi;
    const float* bi = p ? bsi : bmi;

    {
        int l = t >> 2, c = (t & 3) * 16;
        #pragma unroll
        for (int i = 0; i < 4; i++) {
            float4 v = *(const float4*)&g_pooled[(r0 + l) * 64 + c + i * 4];
            X[l][c + i * 4 + 0] = v.x;
            X[l][c + i * 4 + 1] = v.y;
            X[l][c + i * 4 + 2] = v.z;
            X[l][c + i * 4 + 3] = v.w;
        }
    }
    __syncthreads();

    int l  = t & 63;
    int jb = t >> 6;
    for (int jj = 0; jj < 48; jj++) {
        int j = jb * 48 + jj;
        float acc = bi[j];
        #pragma unroll 8
        for (int k = 0; k < 64; k++) acc = fmaf(X[l][k], __ldg(&Wi[j * 64 + k]), acc);
        g_qkv[p][(r0 + l) * 192 + j] = acc;
    }
}

// ---------------------------------------------------------------------------
// K4b: inter attention (L=1024, dh=16). grid (16 qtiles, 4 heads, 2 passes),
// 512 threads: 8 key-chunks of 128 keys, partial online softmax + combine.
// ---------------------------------------------------------------------------
__global__ __launch_bounds__(512) void k4b_attn()
{
    extern __shared__ float sm4b[];
    float* Ks   = sm4b;
    float* Vs   = Ks + 1024 * 16;
    float* pm   = Vs + 1024 * 16;
    float* ps   = pm + 8 * 64;
    float* pacc = ps + 8 * 64;

    int t  = threadIdx.x;
    int kc = t >> 6, qi = t & 63;
    int q0 = blockIdx.x * 64;
    int h  = blockIdx.y;
    int p  = blockIdx.z;
    const float* QKV = g_qkv[p];

    for (int r = t; r < 1024; r += 512) {
        #pragma unroll
        for (int i = 0; i < 4; i++) {
            *(float4*)&Ks[r * 16 + i * 4] =
                *(const float4*)&QKV[(size_t)r * 192 + 64 + h * 16 + i * 4];
            *(float4*)&Vs[r * 16 + i * 4] =
                *(const float4*)&QKV[(size_t)r * 192 + 128 + h * 16 + i * 4];
        }
    }
    __syncthreads();

    float4 q[4];
    #pragma unroll
    for (int i = 0; i < 4; i++)
        q[i] = *(const float4*)&QKV[(size_t)(q0 + qi) * 192 + h * 16 + i * 4];

    float m = -1e30f, ssum = 0.f, acc[16];
    #pragma unroll
    for (int i = 0; i < 16; i++) acc[i] = 0.f;

    int jbase = kc * 128;
    for (int j = jbase; j < jbase + 128; j++) {
        const float4* kr = (const float4*)&Ks[j * 16];
        float4 k0 = kr[0], k1 = kr[1], k2 = kr[2], k3 = kr[3];
        float s = q[0].x * k0.x;
        s = fmaf(q[0].y, k0.y, s); s = fmaf(q[0].z, k0.z, s); s = fmaf(q[0].w, k0.w, s);
        s = fmaf(q[1].x, k1.x, s); s = fmaf(q[1].y, k1.y, s);
        s = fmaf(q[1].z, k1.z, s); s = fmaf(q[1].w, k1.w, s);
        s = fmaf(q[2].x, k2.x, s); s = fmaf(q[2].y, k2.y, s);
        s = fmaf(q[2].z, k2.z, s); s = fmaf(q[2].w, k2.w, s);
        s = fmaf(q[3].x, k3.x, s); s = fmaf(q[3].y, k3.y, s);
        s = fmaf(q[3].z, k3.z, s); s = fmaf(q[3].w, k3.w, s);
        s *= 0.25f;
        const float4* vr = (const float4*)&Vs[j * 16];
        float4 v0 = vr[0], v1 = vr[1], v2 = vr[2], v3 = vr[3];
        float vv[16] = {v0.x, v0.y, v0.z, v0.w, v1.x, v1.y, v1.z, v1.w,
                        v2.x, v2.y, v2.z, v2.w, v3.x, v3.y, v3.z, v3.w};
        if (s <= m) {
            float w = __expf(s - m);
            ssum += w;
            #pragma unroll
            for (int c = 0; c < 16; c++) acc[c] = fmaf(w, vv[c], acc[c]);
        } else {
            float corr = __expf(m - s);
            ssum = fmaf(ssum, corr, 1.f);
            #pragma unroll
            for (int c = 0; c < 16; c++) acc[c] = fmaf(acc[c], corr, vv[c]);
            m = s;
        }
    }
    pm[kc * 64 + qi] = m;
    ps[kc * 64 + qi] = ssum;
    #pragma unroll
    for (int c = 0; c < 16; c++) pacc[(kc * 64 + qi) * 16 + c] = acc[c];
    __syncthreads();

    if (t < 64) {
        float gm = -1e30f;
        #pragma unroll
        for (int i = 0; i < 8; i++) gm = fmaxf(gm, pm[i * 64 + t]);
        float s = 0.f, o[16];
        #pragma unroll
        for (int c = 0; c < 16; c++) o[c] = 0.f;
        #pragma unroll
        for (int i = 0; i < 8; i++) {
            float w = __expf(pm[i * 64 + t] - gm);
            s = fmaf(ps[i * 64 + t], w, s);
            #pragma unroll
            for (int c = 0; c < 16; c++)
                o[c] = fmaf(pacc[(i * 64 + t) * 16 + c], w, o[c]);
        }
        float inv = __fdividef(1.f, s);
        #pragma unroll
        for (int c = 0; c < 16; c++)
            g_attno[p][(size_t)(q0 + t) * 64 + h * 16 + c] = o[c] * inv;
    }
}

// ---------------------------------------------------------------------------
// K4c: inter out-proj, softplus, sample. grid 16, 256 threads.
// ---------------------------------------------------------------------------
__global__ __launch_bounds__(256) void k4c_proj(
    const float* __restrict__ wmo, const float* __restrict__ bmo,
    const float* __restrict__ wso, const float* __restrict__ bso,
    const float* __restrict__ eps_inter)
{
    __shared__ float Om[64][65];
    __shared__ float Os[64][65];
    int t = threadIdx.x;
    int r0 = blockIdx.x * 64;
    {
        int l = t >> 2, c = (t & 3) * 16;
        for (int i = 0; i < 16; i++) {
            Om[l][c + i] = g_attno[0][(size_t)(r0 + l) * 64 + c + i];
            Os[l][c + i] = g_attno[1][(size_t)(r0 + l) * 64 + c + i];
        }
    }
    __syncthreads();

    int lb = t >> 4, db = t & 15;
    float am[4][4], as[4][4];
    #pragma unroll
    for (int i = 0; i < 4; i++)
        #pragma unroll
        for (int j = 0; j < 4; j++) { am[i][j] = 0.f; as[i][j] = 0.f; }

    #pragma unroll 4
    for (int k = 0; k < 64; k++) {
        float om[4], os[4], wmv[4], wsv[4];
        #pragma unroll
        for (int i = 0; i < 4; i++) { om[i] = Om[lb * 4 + i][k]; os[i] = Os[lb * 4 + i][k]; }
        #pragma unroll
        for (int j = 0; j < 4; j++) {
            wmv[j] = __ldg(&wmo[(db * 4 + j) * 64 + k]);
            wsv[j] = __ldg(&wso[(db * 4 + j) * 64 + k]);
        }
        #pragma unroll
        for (int i = 0; i < 4; i++)
            #pragma unroll
            for (int j = 0; j < 4; j++) {
                am[i][j] = fmaf(om[i], wmv[j], am[i][j]);
                as[i][j] = fmaf(os[i], wsv[j], as[i][j]);
            }
    }
    #pragma unroll
    for (int i = 0; i < 4; i++) {
        int gi = r0 + lb * 4 + i;
        #pragma unroll
        for (int j = 0; j < 4; j++) {
            int d = db * 4 + j;
            float mu  = am[i][j] + bmo[d];
            float st  = softplusf(as[i][j] + bso[d] - 5.f);
            g_inter_mu[gi * 64 + d] = mu;
            g_inter_std[gi * 64 + d] = st;
            g_inter_sample[gi * 64 + d] = fmaf(st, eps_inter[gi * 64 + d], mu);
        }
    }
}

// ---------------------------------------------------------------------------
// K2: intra attention per group (QKV precomputed by k2a), out-proj,
// fused with ALL final scatter writes. 1 block / group, 256 threads.
// O and Wo stored TRANSPOSED (stride 68) so the out-proj reads are LDS.128.
// ---------------------------------------------------------------------------
__global__ __launch_bounds__(256) void k2_intra(
    const int* __restrict__ sets,
    const float* __restrict__ wmo, const float* __restrict__ bmo,
    const float* __restrict__ wso, const float* __restrict__ bso,
    const float* __restrict__ eps_intra,
    float* __restrict__ out_ac, float* __restrict__ out_mu, float* __restrict__ out_std)
{
    extern __shared__ float sm[];
    float* QKV  = sm;                    // [64][196]
    float* OT   = QKV + 64 * 196;        // [64 k][68]: OT[c*68 + query]
    float* WoT  = OT + 64 * 68;          // [64 k][68]: WoT[k*68 + outdim]
    float* bout = WoT + 64 * 68;         // [64]
    float* MUb  = bout + 64;             // [64][64]
    int*   rows = (int*)(MUb + 64 * 64); // [64]

    int t = threadIdx.x;
    int g = blockIdx.x;
    if (t < 64) rows[t] = sets[g * 64 + t];
    __syncthreads();

    for (int p = 0; p < 2; p++) {
        const float* wOut = p ? wso : wmo;
        const float* bOut = p ? bso : bmo;
        __syncthreads();
        // load out-proj weights TRANSPOSED: WoT[k][j] = wOut[j*64+k]
        for (int v = t; v < 1024; v += 256) {
            int j = v >> 4; int cv = (v & 15) * 4;
            float4 w4 = *(const float4*)&wOut[j * 64 + cv];
            WoT[(cv + 0) * 68 + j] = w4.x;
            WoT[(cv + 1) * 68 + j] = w4.y;
            WoT[(cv + 2) * 68 + j] = w4.z;
            WoT[(cv + 3) * 68 + j] = w4.w;
        }
        if (t < 64) bout[t] = bOut[t];
        {
            int l = t >> 2, q4 = t & 3;
            const float* src = &g_qkv_all[(size_t)rows[l] * 384 + p * 192 + q4 * 48];
            float* dst = &QKV[l * 196 + q4 * 48];
            #pragma unroll
            for (int i = 0; i < 12; i++)
                *(float4*)&dst[i * 4] = *(const float4*)&src[i * 4];
        }
        __syncthreads();

        // attention: thread = (query i, head h), online softmax (branch form)
        {
            int i = t & 63, h = t >> 6;
            float4 q[4];
            #pragma unroll
            for (int c = 0; c < 4; c++)
                q[c] = *(const float4*)&QKV[i * 196 + h * 16 + c * 4];
            float m = -1e30f, ssum = 0.f, acc[16];
            #pragma unroll
            for (int c = 0; c < 16; c++) acc[c] = 0.f;
            for (int j = 0; j < 64; j++) {
                const float4* kr = (const float4*)&QKV[j * 196 + 64 + h * 16];
                float4 k0 = kr[0], k1 = kr[1], k2 = kr[2], k3 = kr[3];
                float s = q[0].x * k0.x;
                s = fmaf(q[0].y, k0.y, s); s = fmaf(q[0].z, k0.z, s); s = fmaf(q[0].w, k0.w, s);
                s = fmaf(q[1].x, k1.x, s); s = fmaf(q[1].y, k1.y, s);
                s = fmaf(q[1].z, k1.z, s); s = fmaf(q[1].w, k1.w, s);
                s = fmaf(q[2].x, k2.x, s); s = fmaf(q[2].y, k2.y, s);
                s = fmaf(q[2].z, k2.z, s); s = fmaf(q[2].w, k2.w, s);
                s = fmaf(q[3].x, k3.x, s); s = fmaf(q[3].y, k3.y, s);
                s = fmaf(q[3].z, k3.z, s); s = fmaf(q[3].w, k3.w, s);
                s *= 0.25f;
                const float4* vr = (const float4*)&QKV[j * 196 + 128 + h * 16];
                float4 v0 = vr[0], v1 = vr[1], v2 = vr[2], v3 = vr[3];
                float vv[16] = {v0.x, v0.y, v0.z, v0.w, v1.x, v1.y, v1.z, v1.w,
                                v2.x, v2.y, v2.z, v2.w, v3.x, v3.y, v3.z, v3.w};
                if (s <= m) {
                    float w = __expf(s - m);
                    ssum += w;
                    #pragma unroll
                    for (int c = 0; c < 16; c++) acc[c] = fmaf(w, vv[c], acc[c]);
                } else {
                    float corr = __expf(m - s);
                    ssum = fmaf(ssum, corr, 1.f);
                    #pragma unroll
                    for (int c = 0; c < 16; c++) acc[c] = fmaf(acc[c], corr, vv[c]);
                    m = s;
                }
            }
            float inv = __fdividef(1.f, ssum);
            // store TRANSPOSED: OT[(h*16+c)][i]
            #pragma unroll
            for (int c = 0; c < 16; c++) OT[(h * 16 + c) * 68 + i] = acc[c] * inv;
        }
        __syncthreads();

        // out proj via LDS.128: acc[i][j] += OT[k][lb*4+i] * WoT[k][db*4+j]
        {
            int lb = t >> 4, db = t & 15;
            float acc[4][4];
            #pragma unroll
            for (int i = 0; i < 4; i++)
                #pragma unroll
                for (int j = 0; j < 4; j++) acc[i][j] = 0.f;
            #pragma unroll 8
            for (int k = 0; k < 64; k++) {
                float4 ov = *(const float4*)&OT[k * 68 + lb * 4];
                float4 wv = *(const float4*)&WoT[k * 68 + db * 4];
                float ovv[4] = {ov.x, ov.y, ov.z, ov.w};
                float wvv[4] = {wv.x, wv.y, wv.z, wv.w};
                #pragma unroll
                for (int i = 0; i < 4; i++)
                    #pragma unroll
                    for (int j = 0; j < 4; j++)
                        acc[i][j] = fmaf(ovv[i], wvv[j], acc[i][j]);
            }
            int d0 = db * 4;
            #pragma unroll
            for (int i = 0; i < 4; i++) {
                int l = lb * 4 + i;
                int row = rows[l];
                float4 v;
                v.x = acc[i][0] + bout[d0 + 0];
                v.y = acc[i][1] + bout[d0 + 1];
                v.z = acc[i][2] + bout[d0 + 2];
                v.w = acc[i][3] + bout[d0 + 3];
                if (p == 0) {
                    *(float4*)&MUb[l * 64 + d0] = v;
                    *(float4*)&out_mu[(size_t)row * 128 + d0] = v;
                    *(float4*)&out_mu[(size_t)row * 128 + 64 + d0] =
                        *(const float4*)&g_inter_mu[g * 64 + d0];
                    *(float4*)&out_ac[(size_t)row * 640 + 512 + d0] =
                        *(const float4*)&g_inter_sample[g * 64 + d0];
                } else {
                    float4 st;
                    st.x = softplusf(v.x - 5.f);
                    st.y = softplusf(v.y - 5.f);
                    st.z = softplusf(v.z - 5.f);
                    st.w = softplusf(v.w - 5.f);
                    float4 mu4 = *(const float4*)&MUb[l * 64 + d0];
                    float4 ep  = *(const float4*)&eps_intra[(size_t)row * 64 + d0];
                    float4 samp;
                    samp.x = fmaf(st.x, ep.x, mu4.x);
                    samp.y = fmaf(st.y, ep.y, mu4.y);
                    samp.z = fmaf(st.z, ep.z, mu4.z);
                    samp.w = fmaf(st.w, ep.w, mu4.w);
                    *(float4*)&out_std[(size_t)row * 128 + d0] = st;
                    *(float4*)&out_std[(size_t)row * 128 + 64 + d0] =
                        *(const float4*)&g_inter_std[g * 64 + d0];
                    *(float4*)&out_ac[(size_t)row * 640 + 576 + d0] = samp;
                }
            }
        }
    }
}

// ---------------------------------------------------------------------------
extern "C" void kernel_launch(void* const* d_in, const int* in_sizes, int n_in,
                              void* d_out, int out_size)
{
    (void)in_sizes; (void)n_in; (void)out_size;
    const float* obs        = (const float*)d_in[0];
    const int*   sets       = (const int*)  d_in[1];
    const float* eps_intra  = (const float*)d_in[2];
    const float* eps_inter  = (const float*)d_in[3];
    const float* local_w    = (const float*)d_in[4];
    const float* local_b    = (const float*)d_in[5];
    const float* inter_emb_w= (const float*)d_in[6];
    const float* inter_emb_b= (const float*)d_in[7];
    const float* intra_emb_w= (const float*)d_in[8];
    const float* intra_emb_b= (const float*)d_in[9];
    const float* amu_in_w   = (const float*)d_in[10];
    const float* amu_in_b   = (const float*)d_in[11];
    const float* amu_out_w  = (const float*)d_in[12];
    const float* amu_out_b  = (const float*)d_in[13];
    const float* astd_in_w  = (const float*)d_in[14];
    const float* astd_in_b  = (const float*)d_in[15];
    const float* astd_out_w = (const float*)d_in[16];
    const float* astd_out_b = (const float*)d_in[17];
    const float* emu_in_w   = (const float*)d_in[18];
    const float* emu_in_b   = (const float*)d_in[19];
    const float* emu_out_w  = (const float*)d_in[20];
    const float* emu_out_b  = (const float*)d_in[21];
    const float* estd_in_w  = (const float*)d_in[22];
    const float* estd_in_b  = (const float*)d_in[23];
    const float* estd_out_w = (const float*)d_in[24];
    const float* estd_out_b = (const float*)d_in[25];
    const float* attset_w   = (const float*)d_in[26];
    const float* attset_b   = (const float*)d_in[27];

    float* out_ac  = (float*)d_out;
    float* out_mu  = out_ac + (size_t)NN * 640;
    float* out_std = out_mu + (size_t)NN * 128;

    const int k2_smem  = (64*196 + 64*68 + 64*68 + 64 + 64*64) * 4 + 64 * 4;
    const int k4b_smem = (2 * 1024 * 16 + 8 * 64 * 2 + 8 * 64 * 16) * 4;
    cudaFuncSetAttribute(k2_intra, cudaFuncAttributeMaxDynamicSharedMemorySize, k2_smem);
    cudaFuncSetAttribute(k4b_attn, cudaFuncAttributeMaxDynamicSharedMemorySize, k4b_smem);
    cudaFuncSetAttribute(k1_mma, cudaFuncAttributeMaxDynamicSharedMemorySize, K1_SMEM);
    cudaFuncSetAttribute(k2a_qkv_gemm, cudaFuncAttributeMaxDynamicSharedMemorySize, K2A_SMEM);

    // split inputs into bf16 hi/lo
    k0_split_A<<<(NN * OBSD / 4 + 255) / 256, 256>>>((const float4*)obs);
    k0_split_W<<<640, 256>>>(local_w, local_b, inter_emb_w, inter_emb_b,
                             intra_emb_w, intra_emb_b);
    k0_split_Wq<<<384, 64>>>(amu_in_w, amu_in_b, astd_in_w, astd_in_b);

    dim3 g1(512, 10);
    k1_mma<<<g1, 256, K1_SMEM>>>(out_ac);
    dim3 g2a(512, 6);
    k2a_qkv_gemm<<<g2a, 256, K2A_SMEM>>>();

    k3_pool<<<GG, 256>>>(sets, attset_w, attset_b);
    dim3 g4a(16, 2);
    k4a_qkv<<<g4a, 256>>>(emu_in_w, emu_in_b, estd_in_w, estd_in_b);
    dim3 g4b(16, 4, 2);
    k4b_attn<<<g4b, 512, k4b_smem>>>();
    k4c_proj<<<16, 256>>>(emu_out_w, emu_out_b, estd_out_w, estd_out_b, eps_inter);
    k2_intra<<<GG, 256, k2_smem>>>(sets,
                                   amu_out_w, amu_out_b, astd_out_w, astd_out_b,
                                   eps_intra, out_ac, out_mu, out_std);
}